// round 6
// baseline (speedup 1.0000x reference)
#include <cuda_runtime.h>
#include <cooperative_groups.h>
namespace cg = cooperative_groups;

#define NN 100000
#define NE 1200000
#define D 64
#define NL 3
#define NM 5000
#define NO 24
#define BN_EPS 1e-5f
#define NB_SCAN ((NN + 1023) / 1024)
#define HS 68   // smem row stride (floats): 272B = 17*16 (float4-aligned), conflict-free
#define COOP_BLOCKS 592

typedef unsigned long long ull;

// ---------------- scratch ----------------
__device__ __align__(128) float g_X0 [NN * D];
__device__ __align__(128) float g_T  [NN * D];
__device__ __align__(128) float g_XS [NL * NN * D];
__device__ __align__(128) float g_G  [NM * D];
__device__ __align__(128) float g_TG [NM * D];
__device__ __align__(128) float g_stats[4 * 2 * D];   // 4 slots: layers 0..2, ffn=3
__device__ __align__(128) int g_deg   [NN];
__device__ __align__(128) int g_cur   [NN];
__device__ __align__(128) int g_rowptr[NN + 1];
__device__ __align__(128) int g_csr   [NE];
__device__ __align__(128) int g_bsum  [NB_SCAN];
__device__ __align__(128) int g_boff  [NB_SCAN];
__device__ __align__(128) int g_molptr[NM + 1];

// ---------------- f32x2 helpers ----------------
__device__ __forceinline__ ull ffma2(ull a, ull b, ull c) {
    ull d; asm("fma.rn.f32x2 %0, %1, %2, %3;" : "=l"(d) : "l"(a), "l"(b), "l"(c));
    return d;
}
__device__ __forceinline__ ull pack2(float x) {
    ull r; asm("mov.b64 %0, {%1, %1};" : "=l"(r) : "f"(x)); return r;
}
__device__ __forceinline__ float2 u2f(ull v) {
    float2 f; asm("mov.b64 {%0, %1}, %2;" : "=f"(f.x), "=f"(f.y) : "l"(v)); return f;
}
__device__ __forceinline__ ull f2u(float x, float y) {
    ull v; asm("mov.b64 %0, {%1, %2};" : "=l"(v) : "f"(x), "f"(y)); return v;
}

// ---------------- init ----------------
__global__ void k_init() {
    int t = blockIdx.x * blockDim.x + threadIdx.x;
    if (t < NN) { g_deg[t] = 0; g_cur[t] = 0; }
    if (t < 4 * 2 * D) g_stats[t] = 0.f;
}

__global__ void k_embed(const int* __restrict__ atom_ids, const float* __restrict__ embW) {
    int t = blockIdx.x * blockDim.x + threadIdx.x;
    if (t >= NN * 16) return;
    int n = t >> 4, c = (t & 15) << 2;
    int a = __ldg(atom_ids + n);
    *(float4*)(g_X0 + (size_t)n * D + c) = *(const float4*)(embW + (size_t)a * D + c);
}

// ---------------- cooperative CSR build: count + scan + fill -----------------
__global__ void k_csr_coop(const int* __restrict__ src, const int* __restrict__ dst) {
    cg::grid_group grid = cg::this_grid();
    int tid = threadIdx.x, bid = blockIdx.x;
    int gt = bid * 256 + tid, gs = gridDim.x * 256;

    // phase 1: degree count
    for (int e = gt; e < NE; e += gs) atomicAdd(&g_deg[__ldg(dst + e)], 1);
    grid.sync();

    // phase 2: per-chunk inclusive scan (1024 elems per chunk, blocks 0..NB_SCAN-1)
    __shared__ int sh[256];
    if (bid < NB_SCAN) {
        int base = bid * 1024;
        int loc[4]; int s = 0;
        #pragma unroll
        for (int j = 0; j < 4; j++) {
            int i = base + tid * 4 + j;
            int v = (i < NN) ? g_deg[i] : 0;
            s += v; loc[j] = s;
        }
        int excl_in = s;          // thread-local total
        sh[tid] = excl_in; __syncthreads();
        for (int off = 1; off < 256; off <<= 1) {
            int t2 = (tid >= off) ? sh[tid - off] : 0;
            __syncthreads();
            sh[tid] += t2;
            __syncthreads();
        }
        int pre = sh[tid] - excl_in;   // exclusive prefix of this thread
        #pragma unroll
        for (int j = 0; j < 4; j++) {
            int i = base + tid * 4 + j;
            if (i < NN) g_rowptr[i + 1] = pre + loc[j];
        }
        if (tid == 255) g_bsum[bid] = sh[255];
    }
    grid.sync();

    // phase 3: scan chunk totals (one warp of block 0, shfl with carry)
    if (bid == 0 && tid < 32) {
        int carry = 0;
        for (int b = 0; b < NB_SCAN; b += 32) {
            int idx = b + tid;
            int v = (idx < NB_SCAN) ? g_bsum[idx] : 0;
            int x = v;
            #pragma unroll
            for (int off = 1; off < 32; off <<= 1) {
                int y = __shfl_up_sync(0xffffffff, x, off);
                if (tid >= off) x += y;
            }
            if (idx < NB_SCAN) g_boff[idx] = carry + x - v;   // exclusive
            carry += __shfl_sync(0xffffffff, x, 31);
        }
    }
    grid.sync();

    // phase 4: add chunk offsets
    if (gt == 0) g_rowptr[0] = 0;
    for (int i = gt; i < NN; i += gs) g_rowptr[i + 1] += g_boff[i >> 10];
    grid.sync();

    // phase 5: fill CSR
    for (int e = gt; e < NE; e += gs) {
        int d = __ldg(dst + e);
        int pos = g_rowptr[d] + atomicAdd(&g_cur[d], 1);
        g_csr[pos] = __ldg(src + e);
    }
}

__global__ void k_molptr(const int* __restrict__ mol) {
    int t = blockIdx.x * blockDim.x + threadIdx.x;
    if (t >= NN) return;
    int m1 = __ldg(mol + t);
    int m0 = (t == 0) ? -1 : __ldg(mol + t - 1);
    for (int m = m0 + 1; m <= m1; m++) g_molptr[m] = t;
    if (t == NN - 1)
        for (int m = m1 + 1; m <= NM; m++) g_molptr[m] = NN;
}

// ---------------- fused gather + GEMM1 + column-stats (64 rows/block) ----------
__global__ __launch_bounds__(256) void k_gather_gemm(
    const float* __restrict__ X, const float* __restrict__ W,
    const float* __restrict__ bias, float* __restrict__ O, int rows,
    float* __restrict__ stats)
{
    __shared__ __align__(16) float Hs[64 * HS];      // 17408 B
    __shared__ __align__(16) float Ws[D * D];        // 16384 B
    int tid = threadIdx.x;

    for (int i = tid; i < D * D / 4; i += 256) ((float4*)Ws)[i] = ((const float4*)W)[i];

    // gather 64 rows (16 threads/node, 4 batches), 4-way MLP in neighbor loop
    int base = blockIdx.x * 64;
    int c = (tid & 15) << 2;
    #pragma unroll
    for (int b = 0; b < 4; b++) {
        int n = b * 16 + (tid >> 4);          // 0..63
        int node = base + n;
        if (node < rows) {
            int beg = g_rowptr[node], end = g_rowptr[node + 1];
            float4 acc = *(const float4*)(X + (size_t)node * D + c);
            float4 acc2 = make_float4(0.f, 0.f, 0.f, 0.f);
            int e = beg;
            for (; e + 3 < end; e += 4) {
                int s0 = __ldg(&g_csr[e]),     s1 = __ldg(&g_csr[e + 1]);
                int s2 = __ldg(&g_csr[e + 2]), s3 = __ldg(&g_csr[e + 3]);
                float4 v0 = *(const float4*)(X + (size_t)s0 * D + c);
                float4 v1 = *(const float4*)(X + (size_t)s1 * D + c);
                float4 v2 = *(const float4*)(X + (size_t)s2 * D + c);
                float4 v3 = *(const float4*)(X + (size_t)s3 * D + c);
                acc.x  += v0.x + v1.x; acc.y  += v0.y + v1.y;
                acc.z  += v0.z + v1.z; acc.w  += v0.w + v1.w;
                acc2.x += v2.x + v3.x; acc2.y += v2.y + v3.y;
                acc2.z += v2.z + v3.z; acc2.w += v2.w + v3.w;
            }
            for (; e < end; e++) {
                int s0 = __ldg(&g_csr[e]);
                float4 v0 = *(const float4*)(X + (size_t)s0 * D + c);
                acc.x += v0.x; acc.y += v0.y; acc.z += v0.z; acc.w += v0.w;
            }
            acc.x += acc2.x; acc.y += acc2.y; acc.z += acc2.z; acc.w += acc2.w;
            *(float4*)(Hs + n * HS + c) = acc;
        }
    }
    __syncthreads();

    // GEMM: thread = rows {lane, lane+32} x cols [cg*8, cg*8+8)
    int lane = tid & 31;
    int cg_  = tid >> 5;                      // 0..7
    int r0 = base + lane, r1 = r0 + 32;
    bool v0r = (r0 < rows), v1r = (r1 < rows);

    ull a0[4], a1[4];
    const ull* bu = (const ull*)bias;
    #pragma unroll
    for (int q = 0; q < 4; q++) { a0[q] = bu[cg_ * 4 + q]; a1[q] = a0[q]; }

    const float* x0p = Hs + lane * HS;
    const float* x1p = Hs + (lane + 32) * HS;
    const ulonglong2* Wu = (const ulonglong2*)Ws;

    #pragma unroll
    for (int k4 = 0; k4 < 16; k4++) {
        float4 x0 = *(const float4*)(x0p + k4 * 4);
        float4 x1 = *(const float4*)(x1p + k4 * 4);
        float h0[4] = {x0.x, x0.y, x0.z, x0.w};
        float h1[4] = {x1.x, x1.y, x1.z, x1.w};
        #pragma unroll
        for (int j = 0; j < 4; j++) {
            int k = k4 * 4 + j;
            ull p0 = pack2(h0[j]), p1 = pack2(h1[j]);
            ulonglong2 w0 = Wu[k * 16 + cg_ * 2];
            ulonglong2 w1 = Wu[k * 16 + cg_ * 2 + 1];
            a0[0] = ffma2(p0, w0.x, a0[0]); a0[1] = ffma2(p0, w0.y, a0[1]);
            a0[2] = ffma2(p0, w1.x, a0[2]); a0[3] = ffma2(p0, w1.y, a0[3]);
            a1[0] = ffma2(p1, w0.x, a1[0]); a1[1] = ffma2(p1, w0.y, a1[1]);
            a1[2] = ffma2(p1, w1.x, a1[2]); a1[3] = ffma2(p1, w1.y, a1[3]);
        }
    }

    if (v0r) {
        ull* o0 = (ull*)O + (size_t)r0 * 32 + cg_ * 4;
        #pragma unroll
        for (int q = 0; q < 4; q++) o0[q] = a0[q];
    }
    if (v1r) {
        ull* o1 = (ull*)O + (size_t)r1 * 32 + cg_ * 4;
        #pragma unroll
        for (int q = 0; q < 4; q++) o1[q] = a1[q];
    }

    // column stats
    float s[8], ss[8];
    #pragma unroll
    for (int q = 0; q < 4; q++) {
        float2 f0 = u2f(a0[q]), f1 = u2f(a1[q]);
        if (!v0r) { f0.x = 0.f; f0.y = 0.f; }
        if (!v1r) { f1.x = 0.f; f1.y = 0.f; }
        s [2*q]   = f0.x + f1.x;  s [2*q+1] = f0.y + f1.y;
        ss[2*q]   = f0.x*f0.x + f1.x*f1.x;
        ss[2*q+1] = f0.y*f0.y + f1.y*f1.y;
    }
    #pragma unroll
    for (int off = 16; off > 0; off >>= 1) {
        #pragma unroll
        for (int q = 0; q < 8; q++) {
            s[q]  += __shfl_xor_sync(0xffffffff, s[q],  off);
            ss[q] += __shfl_xor_sync(0xffffffff, ss[q], off);
        }
    }
    if (lane == 0) {
        #pragma unroll
        for (int q = 0; q < 8; q++) atomicAdd(&stats[cg_ * 8 + q], s[q]);
    } else if (lane == 1) {
        #pragma unroll
        for (int q = 0; q < 8; q++) atomicAdd(&stats[D + cg_ * 8 + q], ss[q]);
    }
}

// ---------------- GEMM2 (BN inline from stats slot) -------------------------
template<int IN_BN, int OUT_RELU, int STATS>
__global__ __launch_bounds__(256) void k_gemm64(
    const float* __restrict__ X, const float* __restrict__ W,
    const float* __restrict__ bias, float* __restrict__ O, int rows,
    const float* __restrict__ gg, const float* __restrict__ be, float inv_n,
    const float* __restrict__ statsIn, float* __restrict__ statsOut)
{
    __shared__ __align__(16) float Ws[D * D];
    __shared__ float ssa[D], ssb[D];
    int tid = threadIdx.x;
    for (int i = tid; i < D * D / 4; i += 256) ((float4*)Ws)[i] = ((const float4*)W)[i];
    if (IN_BN && tid < D) {
        float mu  = statsIn[tid] * inv_n;
        float var = statsIn[D + tid] * inv_n - mu * mu;
        float rs  = rsqrtf(var + BN_EPS);
        float a   = rs * gg[tid];
        ssa[tid] = a; ssb[tid] = be[tid] - mu * a;
    }
    __syncthreads();

    int r0 = blockIdx.x * 128 + (tid & 63) * 2;
    int r1 = r0 + 1;
    int cg_ = tid >> 6;
    bool act = (r0 < rows);

    ull a0[8], a1[8];
    const ull* bu = (const ull*)bias;
    #pragma unroll
    for (int q = 0; q < 8; q++) { a0[q] = bu[cg_ * 8 + q]; a1[q] = a0[q]; }

    if (act) {
        const float4* x0p = (const float4*)(X + (size_t)r0 * D);
        const float4* x1p = (const float4*)(X + (size_t)r1 * D);
        const ulonglong2* Wu = (const ulonglong2*)Ws;
        #pragma unroll
        for (int k4 = 0; k4 < 16; k4++) {
            float4 x0 = x0p[k4], x1 = x1p[k4];
            if (IN_BN) {
                float4 sa = *(const float4*)(ssa + k4 * 4);
                float4 sb = *(const float4*)(ssb + k4 * 4);
                x0.x = fmaxf(x0.x*sa.x+sb.x, 0.f); x0.y = fmaxf(x0.y*sa.y+sb.y, 0.f);
                x0.z = fmaxf(x0.z*sa.z+sb.z, 0.f); x0.w = fmaxf(x0.w*sa.w+sb.w, 0.f);
                x1.x = fmaxf(x1.x*sa.x+sb.x, 0.f); x1.y = fmaxf(x1.y*sa.y+sb.y, 0.f);
                x1.z = fmaxf(x1.z*sa.z+sb.z, 0.f); x1.w = fmaxf(x1.w*sa.w+sb.w, 0.f);
            }
            float h0[4] = {x0.x, x0.y, x0.z, x0.w};
            float h1[4] = {x1.x, x1.y, x1.z, x1.w};
            #pragma unroll
            for (int j = 0; j < 4; j++) {
                int k = k4 * 4 + j;
                ull p0 = pack2(h0[j]), p1 = pack2(h1[j]);
                #pragma unroll
                for (int p = 0; p < 4; p++) {
                    ulonglong2 w = Wu[k * 16 + cg_ * 4 + p];
                    a0[2*p]   = ffma2(p0, w.x, a0[2*p]);
                    a0[2*p+1] = ffma2(p0, w.y, a0[2*p+1]);
                    a1[2*p]   = ffma2(p1, w.x, a1[2*p]);
                    a1[2*p+1] = ffma2(p1, w.y, a1[2*p+1]);
                }
            }
        }
        ull* o0 = (ull*)O + (size_t)r0 * 32 + cg_ * 8;
        ull* o1 = (ull*)O + (size_t)r1 * 32 + cg_ * 8;
        #pragma unroll
        for (int q = 0; q < 8; q++) {
            if (OUT_RELU) {
                float2 f0 = u2f(a0[q]), f1 = u2f(a1[q]);
                o0[q] = f2u(fmaxf(f0.x,0.f), fmaxf(f0.y,0.f));
                o1[q] = f2u(fmaxf(f1.x,0.f), fmaxf(f1.y,0.f));
            } else {
                o0[q] = a0[q]; o1[q] = a1[q];
            }
        }
    }

    if (STATS) {
        float s[16], ssq[16];
        #pragma unroll
        for (int q = 0; q < 8; q++) {
            float2 f0 = u2f(a0[q]), f1 = u2f(a1[q]);
            if (!act) { f0.x = f0.y = f1.x = f1.y = 0.f; }
            s  [2*q]   = f0.x + f1.x;  s  [2*q+1] = f0.y + f1.y;
            ssq[2*q]   = f0.x*f0.x + f1.x*f1.x;
            ssq[2*q+1] = f0.y*f0.y + f1.y*f1.y;
        }
        #pragma unroll
        for (int off = 16; off > 0; off >>= 1) {
            #pragma unroll
            for (int q = 0; q < 16; q++) {
                s[q]   += __shfl_xor_sync(0xffffffff, s[q],   off);
                ssq[q] += __shfl_xor_sync(0xffffffff, ssq[q], off);
            }
        }
        int lane = tid & 31;
        if (lane == 0) {
            #pragma unroll
            for (int q = 0; q < 16; q++) atomicAdd(&statsOut[cg_ * 16 + q], s[q]);
        } else if (lane == 1) {
            #pragma unroll
            for (int q = 0; q < 16; q++) atomicAdd(&statsOut[D + cg_ * 16 + q], ssq[q]);
        }
    }
}

// JK: O = concat(XS[0..2]) @ jkW + jkb
__global__ __launch_bounds__(256) void k_jk(
    const float* __restrict__ jkW, const float* __restrict__ jkb,
    float* __restrict__ O, int rows)
{
    __shared__ __align__(16) float Ws[D * D];
    int tid = threadIdx.x;
    int r0 = blockIdx.x * 128 + (tid & 63) * 2;
    int r1 = r0 + 1;
    int cg_ = tid >> 6;
    bool act = (r0 < rows);

    ull a0[8], a1[8];
    const ull* bu = (const ull*)jkb;
    #pragma unroll
    for (int q = 0; q < 8; q++) { a0[q] = bu[cg_ * 8 + q]; a1[q] = a0[q]; }

    for (int l = 0; l < NL; l++) {
        __syncthreads();
        for (int i = tid; i < D * D / 4; i += 256)
            ((float4*)Ws)[i] = ((const float4*)(jkW + (size_t)l * D * D))[i];
        __syncthreads();
        if (!act) continue;
        const float4* x0p = (const float4*)(g_XS + ((size_t)l * NN + r0) * D);
        const float4* x1p = (const float4*)(g_XS + ((size_t)l * NN + r1) * D);
        const ulonglong2* Wu = (const ulonglong2*)Ws;
        #pragma unroll
        for (int k4 = 0; k4 < 16; k4++) {
            float4 x0 = x0p[k4], x1 = x1p[k4];
            float h0[4] = {x0.x, x0.y, x0.z, x0.w};
            float h1[4] = {x1.x, x1.y, x1.z, x1.w};
            #pragma unroll
            for (int j = 0; j < 4; j++) {
                int k = k4 * 4 + j;
                ull p0 = pack2(h0[j]), p1 = pack2(h1[j]);
                #pragma unroll
                for (int p = 0; p < 4; p++) {
                    ulonglong2 w = Wu[k * 16 + cg_ * 4 + p];
                    a0[2*p]   = ffma2(p0, w.x, a0[2*p]);
                    a0[2*p+1] = ffma2(p0, w.y, a0[2*p+1]);
                    a1[2*p]   = ffma2(p1, w.x, a1[2*p]);
                    a1[2*p+1] = ffma2(p1, w.y, a1[2*p+1]);
                }
            }
        }
    }
    if (!act) return;
    ull* o0 = (ull*)O + (size_t)r0 * 32 + cg_ * 8;
    ull* o1 = (ull*)O + (size_t)r1 * 32 + cg_ * 8;
    #pragma unroll
    for (int q = 0; q < 8; q++) { o0[q] = a0[q]; o1[q] = a1[q]; }
}

// segmented pool
__global__ void k_pool_seg(const float* __restrict__ XJ) {
    int t = blockIdx.x * 256 + threadIdx.x;
    int m = t >> 4;
    if (m >= NM) return;
    int c = (t & 15) << 2;
    int beg = g_molptr[m], end = g_molptr[m + 1];
    float4 acc = make_float4(0.f, 0.f, 0.f, 0.f);
    for (int n = beg; n < end; n++) {
        float4 v = *(const float4*)(XJ + (size_t)n * D + c);
        acc.x += v.x; acc.y += v.y; acc.z += v.z; acc.w += v.w;
    }
    *(float4*)(g_G + (size_t)m * D + c) = acc;
}

// out = relu(TG*bn) @ (W2 @ oW) + (b2 @ oW + ob), BN inline from stats slot 3
__global__ __launch_bounds__(256) void k_final(
    const float* __restrict__ W2, const float* __restrict__ oW,
    const float* __restrict__ b2, const float* __restrict__ ob,
    const float* __restrict__ gg, const float* __restrict__ be,
    float* __restrict__ out, int rows)
{
    __shared__ float Ws[D * NO];
    __shared__ float bcs[NO], sa[D], sb[D];
    int tid = threadIdx.x;
    const float* statsIn = g_stats + 3 * 2 * D;
    for (int i = tid; i < D * NO; i += 256) {
        int k = i / NO, o = i % NO;
        float sum = 0.f;
        for (int j = 0; j < D; j++) sum += W2[k * D + j] * oW[j * NO + o];
        Ws[i] = sum;
    }
    if (tid < NO) {
        float sum = ob[tid];
        for (int j = 0; j < D; j++) sum += b2[j] * oW[j * NO + tid];
        bcs[tid] = sum;
    }
    if (tid < D) {
        float mu  = statsIn[tid] * (1.0f / NM);
        float var = statsIn[D + tid] * (1.0f / NM) - mu * mu;
        float rs  = rsqrtf(var + BN_EPS);
        float a   = rs * gg[tid];
        sa[tid] = a; sb[tid] = be[tid] - mu * a;
    }
    __syncthreads();
    int row = blockIdx.x * 256 + tid;
    if (row >= rows) return;
    float acc[NO];
    #pragma unroll
    for (int o = 0; o < NO; o++) acc[o] = bcs[o];
    const float* tr = g_TG + (size_t)row * D;
    for (int k = 0; k < D; k++) {
        float h = fmaxf(tr[k] * sa[k] + sb[k], 0.f);
        #pragma unroll
        for (int o = 0; o < NO; o++) acc[o] += h * Ws[k * NO + o];
    }
    float* orow = out + (size_t)row * NO;
    #pragma unroll
    for (int o = 0; o < NO; o++) orow[o] = acc[o];
}

// ---------------- host ----------------
extern "C" void kernel_launch(void* const* d_in, const int* in_sizes, int n_in,
                              void* d_out, int out_size)
{
    const int*   atom_ids = (const int*)  d_in[0];
    const int*   edge     = (const int*)  d_in[1];
    const int*   mol_ids  = (const int*)  d_in[2];
    const float* emb_W    = (const float*)d_in[3];
    const float* gin_W1   = (const float*)d_in[4];
    const float* gin_b1   = (const float*)d_in[5];
    const float* gin_g1   = (const float*)d_in[6];
    const float* gin_be1  = (const float*)d_in[7];
    const float* gin_W2   = (const float*)d_in[8];
    const float* gin_b2   = (const float*)d_in[9];
    const float* jk_W     = (const float*)d_in[10];
    const float* jk_b     = (const float*)d_in[11];
    const float* ffn_W1   = (const float*)d_in[12];
    const float* ffn_b1   = (const float*)d_in[13];
    const float* ffn_g    = (const float*)d_in[14];
    const float* ffn_be   = (const float*)d_in[15];
    const float* ffn_W2   = (const float*)d_in[16];
    const float* ffn_b2   = (const float*)d_in[17];
    const float* out_W    = (const float*)d_in[18];
    const float* out_b    = (const float*)d_in[19];
    float* out = (float*)d_out;

    const int* src = edge;
    const int* dst = edge + NE;

    float *X0, *T, *XS, *G, *TG, *stats;
    cudaGetSymbolAddress((void**)&X0,    g_X0);
    cudaGetSymbolAddress((void**)&T,     g_T);
    cudaGetSymbolAddress((void**)&XS,    g_XS);
    cudaGetSymbolAddress((void**)&G,     g_G);
    cudaGetSymbolAddress((void**)&TG,    g_TG);
    cudaGetSymbolAddress((void**)&stats, g_stats);

    // launch 1, 2
    k_init<<<(NN + 255)/256, 256>>>();
    k_embed<<<(NN*16 + 255)/256, 256>>>(atom_ids, emb_W);

    // launch 3: cooperative CSR build
    {
        void* args[] = { (void*)&src, (void*)&dst };
        cudaLaunchCooperativeKernel((void*)k_csr_coop, dim3(COOP_BLOCKS), dim3(256),
                                    args, 0, (cudaStream_t)0);
    }

    const int GG_GRID   = (NN + 63) / 64;
    const int GEMM_GRID = (NN + 127) / 128;
    // launches 4..9: layers (launch 4 = layer-0 gather_gemm -> ncu capture slot)
    for (int l = 0; l < NL; l++) {
        const float* xin = (l == 0) ? X0 : XS + (size_t)(l-1) * NN * D;
        float* slot = stats + (size_t)l * 2 * D;
        k_gather_gemm<<<GG_GRID, 256>>>(xin, gin_W1 + (size_t)l*D*D, gin_b1 + l*D,
                                        T, NN, slot);
        k_gemm64<1,1,0><<<GEMM_GRID, 256>>>(T, gin_W2 + (size_t)l*D*D, gin_b2 + l*D,
                                            XS + (size_t)l*NN*D, NN,
                                            gin_g1 + l*D, gin_be1 + l*D, 1.0f / NN,
                                            slot, nullptr);
    }

    k_molptr<<<(NN + 255)/256, 256>>>(mol_ids);
    k_jk<<<GEMM_GRID, 256>>>(jk_W, jk_b, X0, NN);
    k_pool_seg<<<(NM*16 + 255)/256, 256>>>(X0);

    float* slot3 = stats + 3 * 2 * D;
    k_gemm64<0,0,1><<<(NM + 127)/128, 256>>>(G, ffn_W1, ffn_b1, TG, NM,
                                             nullptr, nullptr, 0.f,
                                             nullptr, slot3);
    k_final<<<(NM + 255)/256, 256>>>(ffn_W2, out_W, ffn_b2, out_b,
                                     ffn_g, ffn_be, out, NM);
}

// round 8
// speedup vs baseline: 1.3101x; 1.3101x over previous
#include <cuda_runtime.h>
#include <cooperative_groups.h>
namespace cg = cooperative_groups;

#define NN 100000
#define NE 1200000
#define D 64
#define NL 3
#define NM 5000
#define NO 24
#define BN_EPS 1e-5f
#define NB_SCAN ((NN + 1023) / 1024)
#define HS 68          // smem row stride (floats): 272B, float4-aligned, conflict-free
#define RPB 128        // rows per block in unified GEMM
#define COOP_BLOCKS 592
#define SMEM_G ((RPB * HS + D * D) * 4)   // 51200 B dynamic

typedef unsigned long long ull;

// ---------------- scratch ----------------
__device__ __align__(128) float g_X0 [NN * D];
__device__ __align__(128) float g_T  [NN * D];
__device__ __align__(128) float g_XS [NL * NN * D];
__device__ __align__(128) float g_G  [NM * D];
__device__ __align__(128) float g_TG [NM * D];
__device__ __align__(128) float g_stats[4 * 2 * D];
__device__ __align__(128) int g_deg   [NN];
__device__ __align__(128) int g_cur   [NN];
__device__ __align__(128) int g_rowptr[NN + 1];
__device__ __align__(128) int g_csr   [NE];
__device__ __align__(128) int g_bsum  [NB_SCAN];
__device__ __align__(128) int g_boff  [NB_SCAN];
__device__ __align__(128) int g_molptr[NM + 1];

// ---------------- f32x2 helpers ----------------
__device__ __forceinline__ ull ffma2(ull a, ull b, ull c) {
    ull d; asm("fma.rn.f32x2 %0, %1, %2, %3;" : "=l"(d) : "l"(a), "l"(b), "l"(c));
    return d;
}
__device__ __forceinline__ ull pack2(float x) {
    ull r; asm("mov.b64 %0, {%1, %1};" : "=l"(r) : "f"(x)); return r;
}
__device__ __forceinline__ float2 u2f(ull v) {
    float2 f; asm("mov.b64 {%0, %1}, %2;" : "=f"(f.x), "=f"(f.y) : "l"(v)); return f;
}

// ---------------- init ----------------
__global__ void k_init() {
    int t = blockIdx.x * blockDim.x + threadIdx.x;
    if (t < NN) { g_deg[t] = 0; g_cur[t] = 0; }
    if (t < 4 * 2 * D) g_stats[t] = 0.f;
}

__global__ void k_embed(const int* __restrict__ atom_ids, const float* __restrict__ embW) {
    int t = blockIdx.x * blockDim.x + threadIdx.x;
    if (t >= NN * 16) return;
    int n = t >> 4, c = (t & 15) << 2;
    int a = __ldg(atom_ids + n);
    *(float4*)(g_X0 + (size_t)n * D + c) = *(const float4*)(embW + (size_t)a * D + c);
}

// ---------------- cooperative CSR build -----------------
__global__ void k_csr_coop(const int* __restrict__ src, const int* __restrict__ dst) {
    cg::grid_group grid = cg::this_grid();
    int tid = threadIdx.x, bid = blockIdx.x;
    int gt = bid * 256 + tid, gs = gridDim.x * 256;

    for (int e = gt; e < NE; e += gs) atomicAdd(&g_deg[__ldg(dst + e)], 1);
    grid.sync();

    __shared__ int sh[256];
    if (bid < NB_SCAN) {
        int base = bid * 1024;
        int loc[4]; int s = 0;
        #pragma unroll
        for (int j = 0; j < 4; j++) {
            int i = base + tid * 4 + j;
            int v = (i < NN) ? g_deg[i] : 0;
            s += v; loc[j] = s;
        }
        int excl_in = s;
        sh[tid] = excl_in; __syncthreads();
        for (int off = 1; off < 256; off <<= 1) {
            int t2 = (tid >= off) ? sh[tid - off] : 0;
            __syncthreads();
            sh[tid] += t2;
            __syncthreads();
        }
        int pre = sh[tid] - excl_in;
        #pragma unroll
        for (int j = 0; j < 4; j++) {
            int i = base + tid * 4 + j;
            if (i < NN) g_rowptr[i + 1] = pre + loc[j];
        }
        if (tid == 255) g_bsum[bid] = sh[255];
    }
    grid.sync();

    if (bid == 0 && tid < 32) {
        int carry = 0;
        for (int b = 0; b < NB_SCAN; b += 32) {
            int idx = b + tid;
            int v = (idx < NB_SCAN) ? g_bsum[idx] : 0;
            int x = v;
            #pragma unroll
            for (int off = 1; off < 32; off <<= 1) {
                int y = __shfl_up_sync(0xffffffff, x, off);
                if (tid >= off) x += y;
            }
            if (idx < NB_SCAN) g_boff[idx] = carry + x - v;
            carry += __shfl_sync(0xffffffff, x, 31);
        }
    }
    grid.sync();

    if (gt == 0) g_rowptr[0] = 0;
    for (int i = gt; i < NN; i += gs) g_rowptr[i + 1] += g_boff[i >> 10];
    grid.sync();

    for (int e = gt; e < NE; e += gs) {
        int d = __ldg(dst + e);
        int pos = g_rowptr[d] + atomicAdd(&g_cur[d], 1);
        g_csr[pos] = __ldg(src + e);
    }
}

__global__ void k_molptr(const int* __restrict__ mol) {
    int t = blockIdx.x * blockDim.x + threadIdx.x;
    if (t >= NN) return;
    int m1 = __ldg(mol + t);
    int m0 = (t == 0) ? -1 : __ldg(mol + t - 1);
    for (int m = m0 + 1; m <= m1; m++) g_molptr[m] = t;
    if (t == NN - 1)
        for (int m = m1 + 1; m <= NM; m++) g_molptr[m] = NN;
}

// ============================================================================
// Unified GEMM kernel: 128 rows/block, 4 rows x 8 cols per thread.
//   GATHER: stage Hs[n] = X[node] + sum_neighbors X[s]   (else copy X rows)
//   IN_BN : BN(scale/shift from statsIn)+relu applied during stage
//   OUT_RELU: relu on output store
//   STATS : column sum/sumsq of output accumulated into statsOut
//   NPASS : accumulate over NPASS (X + ps*xStride) @ (W + ps*wStride)   (JK=3)
// ============================================================================
template<int GATHER, int IN_BN, int OUT_RELU, int STATS, int NPASS>
__global__ __launch_bounds__(256) void k_gemm(
    const float* __restrict__ X, const float* __restrict__ W,
    const float* __restrict__ bias, float* __restrict__ O, int rows,
    const float* __restrict__ statsIn, float* __restrict__ statsOut,
    const float* __restrict__ gg, const float* __restrict__ be, float inv_n,
    size_t xStride, size_t wStride)
{
    extern __shared__ __align__(16) float dsm[];
    float* Hs = dsm;                    // RPB * HS
    float* Ws = dsm + RPB * HS;         // D * D
    __shared__ float ssa[D], ssb[D];
    int tid = threadIdx.x;
    int base = blockIdx.x * RPB;
    int lane = tid & 31, cgp = tid >> 5;        // 8 column groups

    if (IN_BN && tid < D) {
        float mu  = statsIn[tid] * inv_n;
        float var = statsIn[D + tid] * inv_n - mu * mu;
        float rs  = rsqrtf(var + BN_EPS);
        float a   = rs * gg[tid];
        ssa[tid] = a; ssb[tid] = be[tid] - mu * a;
    }

    ull a0[4], a1[4], a2[4], a3[4];
    const ull* bu = (const ull*)bias;
    #pragma unroll
    for (int q = 0; q < 4; q++) {
        a0[q] = bu[cgp * 4 + q]; a1[q] = a0[q]; a2[q] = a0[q]; a3[q] = a0[q];
    }

    for (int ps = 0; ps < NPASS; ps++) {
        __syncthreads();
        // load W pass
        const float* Wp = W + (size_t)ps * wStride;
        for (int i = tid; i < D * D / 4; i += 256)
            ((float4*)Ws)[i] = ((const float4*)Wp)[i];

        // stage Hs
        if (GATHER) {
            int c = (tid & 15) << 2;
            #pragma unroll
            for (int b = 0; b < 8; b++) {
                int n = b * 16 + (tid >> 4);          // 0..127
                int node = base + n;
                if (node < rows) {
                    int beg = g_rowptr[node], end = g_rowptr[node + 1];
                    float4 acc = *(const float4*)(X + (size_t)node * D + c);
                    float4 acc2 = make_float4(0.f, 0.f, 0.f, 0.f);
                    int e = beg;
                    for (; e + 3 < end; e += 4) {
                        int s0 = __ldg(&g_csr[e]),     s1 = __ldg(&g_csr[e + 1]);
                        int s2 = __ldg(&g_csr[e + 2]), s3 = __ldg(&g_csr[e + 3]);
                        float4 v0 = *(const float4*)(X + (size_t)s0 * D + c);
                        float4 v1 = *(const float4*)(X + (size_t)s1 * D + c);
                        float4 v2 = *(const float4*)(X + (size_t)s2 * D + c);
                        float4 v3 = *(const float4*)(X + (size_t)s3 * D + c);
                        acc.x  += v0.x + v1.x; acc.y  += v0.y + v1.y;
                        acc.z  += v0.z + v1.z; acc.w  += v0.w + v1.w;
                        acc2.x += v2.x + v3.x; acc2.y += v2.y + v3.y;
                        acc2.z += v2.z + v3.z; acc2.w += v2.w + v3.w;
                    }
                    for (; e < end; e++) {
                        int s0 = __ldg(&g_csr[e]);
                        float4 v0 = *(const float4*)(X + (size_t)s0 * D + c);
                        acc.x += v0.x; acc.y += v0.y; acc.z += v0.z; acc.w += v0.w;
                    }
                    acc.x += acc2.x; acc.y += acc2.y; acc.z += acc2.z; acc.w += acc2.w;
                    *(float4*)(Hs + n * HS + c) = acc;
                }
            }
        } else {
            const float* Xp = X + (size_t)ps * xStride;
            #pragma unroll
            for (int it = 0; it < RPB * 16 / 256; it++) {
                int i = it * 256 + tid;
                int r = i >> 4, c = (i & 15) << 2;
                int row = base + r;
                if (row < rows) {
                    float4 v = *(const float4*)(Xp + (size_t)row * D + c);
                    if (IN_BN) {
                        v.x = fmaxf(v.x * ssa[c]   + ssb[c],   0.f);
                        v.y = fmaxf(v.y * ssa[c+1] + ssb[c+1], 0.f);
                        v.z = fmaxf(v.z * ssa[c+2] + ssb[c+2], 0.f);
                        v.w = fmaxf(v.w * ssa[c+3] + ssb[c+3], 0.f);
                    }
                    *(float4*)(Hs + r * HS + c) = v;
                }
            }
        }
        __syncthreads();

        // GEMM: rows lane, lane+32, lane+64, lane+96; cols [cgp*8, cgp*8+8)
        const float* x0p = Hs + lane * HS;
        const float* x1p = x0p + 32 * HS;
        const float* x2p = x0p + 64 * HS;
        const float* x3p = x0p + 96 * HS;
        const ulonglong2* Wu = (const ulonglong2*)Ws;
        #pragma unroll
        for (int k4 = 0; k4 < 16; k4++) {
            float4 x0 = *(const float4*)(x0p + k4 * 4);
            float4 x1 = *(const float4*)(x1p + k4 * 4);
            float4 x2 = *(const float4*)(x2p + k4 * 4);
            float4 x3 = *(const float4*)(x3p + k4 * 4);
            float h0[4] = {x0.x, x0.y, x0.z, x0.w};
            float h1[4] = {x1.x, x1.y, x1.z, x1.w};
            float h2[4] = {x2.x, x2.y, x2.z, x2.w};
            float h3[4] = {x3.x, x3.y, x3.z, x3.w};
            #pragma unroll
            for (int j = 0; j < 4; j++) {
                int k = k4 * 4 + j;
                ulonglong2 w0 = Wu[k * 16 + cgp * 2];       // broadcast in warp
                ulonglong2 w1 = Wu[k * 16 + cgp * 2 + 1];
                ull p0 = pack2(h0[j]), p1 = pack2(h1[j]);
                ull p2 = pack2(h2[j]), p3 = pack2(h3[j]);
                a0[0] = ffma2(p0, w0.x, a0[0]); a0[1] = ffma2(p0, w0.y, a0[1]);
                a0[2] = ffma2(p0, w1.x, a0[2]); a0[3] = ffma2(p0, w1.y, a0[3]);
                a1[0] = ffma2(p1, w0.x, a1[0]); a1[1] = ffma2(p1, w0.y, a1[1]);
                a1[2] = ffma2(p1, w1.x, a1[2]); a1[3] = ffma2(p1, w1.y, a1[3]);
                a2[0] = ffma2(p2, w0.x, a2[0]); a2[1] = ffma2(p2, w0.y, a2[1]);
                a2[2] = ffma2(p2, w1.x, a2[2]); a2[3] = ffma2(p2, w1.y, a2[3]);
                a3[0] = ffma2(p3, w0.x, a3[0]); a3[1] = ffma2(p3, w0.y, a3[1]);
                a3[2] = ffma2(p3, w1.x, a3[2]); a3[3] = ffma2(p3, w1.y, a3[3]);
            }
        }
    }

    // store output
    ull* aa[4] = {a0, a1, a2, a3};
    #pragma unroll
    for (int ri = 0; ri < 4; ri++) {
        int row = base + lane + ri * 32;
        if (row < rows) {
            ull* orow = (ull*)O + (size_t)row * 32 + cgp * 4;
            #pragma unroll
            for (int q = 0; q < 4; q++) {
                ull v = aa[ri][q];
                if (OUT_RELU) {
                    float2 f = u2f(v);
                    float2 g2 = make_float2(fmaxf(f.x, 0.f), fmaxf(f.y, 0.f));
                    ull t; asm("mov.b64 %0, {%1, %2};" : "=l"(t) : "f"(g2.x), "f"(g2.y));
                    v = t;
                }
                orow[q] = v;
            }
        }
    }

    if (STATS) {
        float s[8], ss[8];
        #pragma unroll
        for (int q = 0; q < 8; q++) { s[q] = 0.f; ss[q] = 0.f; }
        #pragma unroll
        for (int ri = 0; ri < 4; ri++) {
            bool v = (base + lane + ri * 32) < rows;
            #pragma unroll
            for (int q = 0; q < 4; q++) {
                float2 f = u2f(aa[ri][q]);
                if (!v) { f.x = 0.f; f.y = 0.f; }
                s [2*q]   += f.x;       s [2*q+1] += f.y;
                ss[2*q]   += f.x * f.x; ss[2*q+1] += f.y * f.y;
            }
        }
        #pragma unroll
        for (int off = 16; off > 0; off >>= 1) {
            #pragma unroll
            for (int q = 0; q < 8; q++) {
                s[q]  += __shfl_xor_sync(0xffffffff, s[q],  off);
                ss[q] += __shfl_xor_sync(0xffffffff, ss[q], off);
            }
        }
        if (lane == 0) {
            #pragma unroll
            for (int q = 0; q < 8; q++) atomicAdd(&statsOut[cgp * 8 + q], s[q]);
        } else if (lane == 1) {
            #pragma unroll
            for (int q = 0; q < 8; q++) atomicAdd(&statsOut[D + cgp * 8 + q], ss[q]);
        }
    }
}

// segmented pool
__global__ void k_pool_seg(const float* __restrict__ XJ) {
    int t = blockIdx.x * 256 + threadIdx.x;
    int m = t >> 4;
    if (m >= NM) return;
    int c = (t & 15) << 2;
    int beg = g_molptr[m], end = g_molptr[m + 1];
    float4 acc = make_float4(0.f, 0.f, 0.f, 0.f);
    for (int n = beg; n < end; n++) {
        float4 v = *(const float4*)(XJ + (size_t)n * D + c);
        acc.x += v.x; acc.y += v.y; acc.z += v.z; acc.w += v.w;
    }
    *(float4*)(g_G + (size_t)m * D + c) = acc;
}

// out = relu(TG*bn) @ (W2 @ oW) + (b2 @ oW + ob)
__global__ __launch_bounds__(256) void k_final(
    const float* __restrict__ W2, const float* __restrict__ oW,
    const float* __restrict__ b2, const float* __restrict__ ob,
    const float* __restrict__ gg, const float* __restrict__ be,
    float* __restrict__ out, int rows)
{
    __shared__ float Ws[D * NO];
    __shared__ float bcs[NO], sa[D], sb[D];
    int tid = threadIdx.x;
    const float* statsIn = g_stats + 3 * 2 * D;
    for (int i = tid; i < D * NO; i += 256) {
        int k = i / NO, o = i % NO;
        float sum = 0.f;
        for (int j = 0; j < D; j++) sum += W2[k * D + j] * oW[j * NO + o];
        Ws[i] = sum;
    }
    if (tid < NO) {
        float sum = ob[tid];
        for (int j = 0; j < D; j++) sum += b2[j] * oW[j * NO + tid];
        bcs[tid] = sum;
    }
    if (tid < D) {
        float mu  = statsIn[tid] * (1.0f / NM);
        float var = statsIn[D + tid] * (1.0f / NM) - mu * mu;
        float rs  = rsqrtf(var + BN_EPS);
        float a   = rs * gg[tid];
        sa[tid] = a; sb[tid] = be[tid] - mu * a;
    }
    __syncthreads();
    int row = blockIdx.x * 256 + tid;
    if (row >= rows) return;
    float acc[NO];
    #pragma unroll
    for (int o = 0; o < NO; o++) acc[o] = bcs[o];
    const float* tr = g_TG + (size_t)row * D;
    for (int k = 0; k < D; k++) {
        float h = fmaxf(tr[k] * sa[k] + sb[k], 0.f);
        #pragma unroll
        for (int o = 0; o < NO; o++) acc[o] += h * Ws[k * NO + o];
    }
    float* orow = out + (size_t)row * NO;
    #pragma unroll
    for (int o = 0; o < NO; o++) orow[o] = acc[o];
}

// ---------------- host ----------------
extern "C" void kernel_launch(void* const* d_in, const int* in_sizes, int n_in,
                              void* d_out, int out_size)
{
    const int*   atom_ids = (const int*)  d_in[0];
    const int*   edge     = (const int*)  d_in[1];
    const int*   mol_ids  = (const int*)  d_in[2];
    const float* emb_W    = (const float*)d_in[3];
    const float* gin_W1   = (const float*)d_in[4];
    const float* gin_b1   = (const float*)d_in[5];
    const float* gin_g1   = (const float*)d_in[6];
    const float* gin_be1  = (const float*)d_in[7];
    const float* gin_W2   = (const float*)d_in[8];
    const float* gin_b2   = (const float*)d_in[9];
    const float* jk_W     = (const float*)d_in[10];
    const float* jk_b     = (const float*)d_in[11];
    const float* ffn_W1   = (const float*)d_in[12];
    const float* ffn_b1   = (const float*)d_in[13];
    const float* ffn_g    = (const float*)d_in[14];
    const float* ffn_be   = (const float*)d_in[15];
    const float* ffn_W2   = (const float*)d_in[16];
    const float* ffn_b2   = (const float*)d_in[17];
    const float* out_W    = (const float*)d_in[18];
    const float* out_b    = (const float*)d_in[19];
    float* out = (float*)d_out;

    const int* src = edge;
    const int* dst = edge + NE;

    float *X0, *T, *XS, *G, *TG, *stats;
    cudaGetSymbolAddress((void**)&X0,    g_X0);
    cudaGetSymbolAddress((void**)&T,     g_T);
    cudaGetSymbolAddress((void**)&XS,    g_XS);
    cudaGetSymbolAddress((void**)&G,     g_G);
    cudaGetSymbolAddress((void**)&TG,    g_TG);
    cudaGetSymbolAddress((void**)&stats, g_stats);

    cudaFuncSetAttribute(k_gemm<1,0,0,1,1>, cudaFuncAttributeMaxDynamicSharedMemorySize, SMEM_G);
    cudaFuncSetAttribute(k_gemm<0,1,1,0,1>, cudaFuncAttributeMaxDynamicSharedMemorySize, SMEM_G);
    cudaFuncSetAttribute(k_gemm<0,0,0,0,NL>, cudaFuncAttributeMaxDynamicSharedMemorySize, SMEM_G);
    cudaFuncSetAttribute(k_gemm<0,0,0,1,1>, cudaFuncAttributeMaxDynamicSharedMemorySize, SMEM_G);

    k_init<<<(NN + 255)/256, 256>>>();
    k_embed<<<(NN*16 + 255)/256, 256>>>(atom_ids, emb_W);
    {
        void* args[] = { (void*)&src, (void*)&dst };
        cudaLaunchCooperativeKernel((void*)k_csr_coop, dim3(COOP_BLOCKS), dim3(256),
                                    args, 0, (cudaStream_t)0);
    }

    const int GRID = (NN + RPB - 1) / RPB;
    for (int l = 0; l < NL; l++) {
        const float* xin = (l == 0) ? X0 : XS + (size_t)(l-1) * NN * D;
        float* slot = stats + (size_t)l * 2 * D;
        // gemm1: gather + GEMM + stats  -> T
        k_gemm<1,0,0,1,1><<<GRID, 256, SMEM_G>>>(
            xin, gin_W1 + (size_t)l*D*D, gin_b1 + l*D, T, NN,
            nullptr, slot, nullptr, nullptr, 0.f, 0, 0);
        // gemm2: BN+relu stage + GEMM + relu -> XS[l]
        k_gemm<0,1,1,0,1><<<GRID, 256, SMEM_G>>>(
            T, gin_W2 + (size_t)l*D*D, gin_b2 + l*D, XS + (size_t)l*NN*D, NN,
            slot, nullptr, gin_g1 + l*D, gin_be1 + l*D, 1.0f / NN, 0, 0);
    }

    k_molptr<<<(NN + 255)/256, 256>>>(mol_ids);
    // JK: 3-pass accumulate -> X0
    k_gemm<0,0,0,0,NL><<<GRID, 256, SMEM_G>>>(
        XS, jk_W, jk_b, X0, NN,
        nullptr, nullptr, nullptr, nullptr, 0.f, (size_t)NN * D, (size_t)D * D);

    k_pool_seg<<<(NM*16 + 255)/256, 256>>>(X0);

    float* slot3 = stats + 3 * 2 * D;
    k_gemm<0,0,0,1,1><<<(NM + RPB - 1)/RPB, 256, SMEM_G>>>(
        G, ffn_W1, ffn_b1, TG, NM,
        nullptr, slot3, nullptr, nullptr, 0.f, 0, 0);

    k_final<<<(NM + 255)/256, 256>>>(ffn_W2, out_W, ffn_b2, out_b,
                                     ffn_g, ffn_be, out, NM);
}